// round 3
// baseline (speedup 1.0000x reference)
#include <cuda_runtime.h>

#define NN 500000   // N_NODES upper bound
#define EE 16000000 // N_EDGES upper bound
#define TB 256
#define EPT 8       // edges per thread in scatter kernels

// Scratch (no cudaMalloc allowed).
__device__ int    g_is64;       // 1 if edge_index is int64, 0 if int32
__device__ int2   g_edge[EE];   // packed (src, dst), decoded to int32
__device__ float  g_deg [NN];   // degree (float; exact for counts < 2^24)
__device__ float  g_dinv[NN];   // deg^{-1/2}
__device__ float  g_v   [NN];   // dinv[i] * x[i]            (gather source, layer 1)
__device__ float  g_s   [NN];   // layer-1 accumulator (init = self-loop term)
__device__ float4 g_h2d [NN];   // dinv[i] * (relu(pre1)@W2) (gather source, layer 2)

// ---------------- dtype probe ----------------
// Interpreted as int64, genuine int64 indices are always in [0, n).
// int32 data misread as int64 gives lo + hi*2^32, out of range unless hi==0.
__global__ void k_probe(const void* ei, int E, int n) {
    __shared__ int ok;
    if (threadIdx.x == 0) ok = 1;
    __syncthreads();
    const long long* p = (const long long*)ei;
    long long stride = E / blockDim.x;
    if (stride < 1) stride = 1;
    long long idx = (long long)threadIdx.x * stride;
    if (idx < E) {  // first E int64 slots are in-bounds under BOTH interpretations
        long long v = p[idx];
        if (v < 0 || v >= (long long)n) ok = 0;
    }
    __syncthreads();
    if (threadIdx.x == 0) g_is64 = ok;
}

// ---------------- node kernels ----------------

__global__ void k_init_deg(int n) {
    int i = blockIdx.x * blockDim.x + threadIdx.x;
    if (i < n) g_deg[i] = 1.0f;              // self-loop
}

__global__ void k_dinv(const float* __restrict__ x, int n) {
    int i = blockIdx.x * blockDim.x + threadIdx.x;
    if (i < n) {
        float di = rsqrtf(g_deg[i]);         // deg >= 1 always (self-loop)
        g_dinv[i] = di;
        float v = di * x[i];
        g_v[i] = v;
        g_s[i] = v;                          // self-loop contribution, layer 1
    }
}

// pre1 = dinv*s ; h = relu(pre1*W1 + b1) ; h2 = h@W2 ; h2d = dinv*h2
// out init = h2d (self-loop contribution of layer 2, pre final-dinv scaling)
__global__ void k_node_mid(const float* __restrict__ W1, const float* __restrict__ b1,
                           const float* __restrict__ W2, const float* __restrict__ b2,
                           float4* __restrict__ out, int n) {
    int i = blockIdx.x * blockDim.x + threadIdx.x;
    if (i >= n) return;
    float di  = g_dinv[i];
    float pre = di * g_s[i];
    float h[4];
#pragma unroll
    for (int c = 0; c < 4; c++)
        h[c] = fmaxf(fmaf(pre, __ldg(&W1[c]), __ldg(&b1[c])), 0.0f);
    float h2[4];
#pragma unroll
    for (int c = 0; c < 4; c++) {
        float acc = h[0] * __ldg(&W2[0 * 4 + c]);
        acc = fmaf(h[1], __ldg(&W2[1 * 4 + c]), acc);
        acc = fmaf(h[2], __ldg(&W2[2 * 4 + c]), acc);
        acc = fmaf(h[3], __ldg(&W2[3 * 4 + c]), acc);
        h2[c] = di * acc;
    }
    float4 v = make_float4(h2[0], h2[1], h2[2], h2[3]);
    g_h2d[i] = v;
    out[i]   = v;                            // accumulate layer-2 messages here
}

__global__ void k_final(const float* __restrict__ b2, float4* __restrict__ out, int n) {
    int i = blockIdx.x * blockDim.x + threadIdx.x;
    if (i >= n) return;
    float di = g_dinv[i];
    float4 o = out[i];
    out[i] = make_float4(fmaf(di, o.x, __ldg(&b2[0])),
                         fmaf(di, o.y, __ldg(&b2[1])),
                         fmaf(di, o.z, __ldg(&b2[2])),
                         fmaf(di, o.w, __ldg(&b2[3])));
}

// ---------------- edge kernels ----------------

// Decode indices (either dtype) into packed int2 + accumulate degree.
__global__ void k_convert_deg(const void* __restrict__ ei, int E, int n) {
    int is64 = g_is64;
    int e0 = blockIdx.x * blockDim.x * 4 + threadIdx.x;
#pragma unroll
    for (int k = 0; k < 4; k++) {
        int e = e0 + k * blockDim.x;
        if (e < E) {
            int s, d;
            if (is64) {
                const long long* p = (const long long*)ei;
                s = (int)p[e];
                d = (int)p[e + E];
            } else {
                const int* p = (const int*)ei;
                s = p[e];
                d = p[e + E];
            }
            g_edge[e] = make_int2(s, d);
            if ((unsigned)d < (unsigned)n) atomicAdd(&g_deg[d], 1.0f);
        }
    }
}

__global__ void __launch_bounds__(TB) k_scatter1(int E) {
    int e0 = blockIdx.x * blockDim.x * EPT + threadIdx.x;
    int2 ed[EPT];
#pragma unroll
    for (int k = 0; k < EPT; k++) {
        int e = e0 + k * blockDim.x;
        if (e < E) ed[k] = g_edge[e];
        else       ed[k] = make_int2(0, -1);
    }
#pragma unroll
    for (int k = 0; k < EPT; k++) {
        if (ed[k].y >= 0) {
            float v = __ldg(&g_v[ed[k].x]);
            atomicAdd(&g_s[ed[k].y], v);
        }
    }
}

__global__ void __launch_bounds__(TB) k_scatter2(float4* __restrict__ out, int E) {
    int e0 = blockIdx.x * blockDim.x * EPT + threadIdx.x;
    int2 ed[EPT];
#pragma unroll
    for (int k = 0; k < EPT; k++) {
        int e = e0 + k * blockDim.x;
        if (e < E) ed[k] = g_edge[e];
        else       ed[k] = make_int2(0, -1);
    }
#pragma unroll
    for (int k = 0; k < EPT; k++) {
        if (ed[k].y >= 0) {
            float4 m = __ldg(&g_h2d[ed[k].x]);
            float* p = reinterpret_cast<float*>(&out[ed[k].y]);
            asm volatile("red.global.add.v4.f32 [%0], {%1,%2,%3,%4};"
                         :: "l"(p), "f"(m.x), "f"(m.y), "f"(m.z), "f"(m.w)
                         : "memory");
        }
    }
}

// ---------------- launch ----------------

extern "C" void kernel_launch(void* const* d_in, const int* in_sizes, int n_in,
                              void* d_out, int out_size) {
    const float* x  = (const float*)d_in[0];
    const void*  ei = d_in[1];                 // [2, E], int32 or int64
    const float* W1 = (const float*)d_in[2];
    const float* b1 = (const float*)d_in[3];
    const float* W2 = (const float*)d_in[4];
    const float* b2 = (const float*)d_in[5];
    float4* out = (float4*)d_out;

    int n = in_sizes[0];            // N nodes (C_in = 1)
    int E = in_sizes[1] / 2;        // element count is dtype-independent

    int nb_node  = (n + TB - 1) / TB;
    int nb_conv  = (E + TB * 4 - 1) / (TB * 4);
    int nb_edge  = (E + TB * EPT - 1) / (TB * EPT);

    k_probe       <<<1, TB>>>(ei, E, n);
    k_init_deg    <<<nb_node, TB>>>(n);
    k_convert_deg <<<nb_conv, TB>>>(ei, E, n);
    k_dinv        <<<nb_node, TB>>>(x, n);
    k_scatter1    <<<nb_edge, TB>>>(E);
    k_node_mid    <<<nb_node, TB>>>(W1, b1, W2, b2, out, n);
    k_scatter2    <<<nb_edge, TB>>>(out, E);
    k_final       <<<nb_node, TB>>>(b2, out, n);
}

// round 4
// speedup vs baseline: 1.1110x; 1.1110x over previous
#include <cuda_runtime.h>

#define NN 500000   // N_NODES upper bound
#define TB 256
#define EPT 4       // edges per thread in edge kernels

// Scratch (no cudaMalloc allowed).
__device__ int    g_is64;        // 1 if edge_index is int64, 0 if int32
__device__ int    g_b1zero;      // 1 if b1 == 0 (enables scalar layer-2 path)
__device__ float  g_deg [NN];    // degree (float; exact for counts < 2^24)
__device__ float  g_dinv[NN];    // deg^{-1/2}
__device__ float  g_v   [NN];    // dinv[i] * x[i]          (gather source, layer 1)
__device__ float  g_s   [NN];    // layer-1 accumulator (init = self-loop term)
__device__ float  g_val [NN];    // dinv[i]^2 * s[i] = dinv*pre   (gather, layer 2 fast path)
__device__ float  g_spos[NN];    // Σ max(val[s],0) at dst  (init = self-loop)
__device__ float  g_sneg[NN];    // Σ max(-val[s],0) at dst (init = self-loop)
__device__ float4 g_h2d [NN];    // dinv[i]*(relu(pre)@W2)  (gather, fallback path)

// ---------------- probes ----------------
// Interpreted as int64, genuine int64 indices are always in [0, n).
// int32 data misread as int64 gives lo + hi*2^32, out of range unless hi==0.
__global__ void k_probe(const void* ei, int E, int n, const float* __restrict__ b1) {
    __shared__ int ok;
    if (threadIdx.x == 0) ok = 1;
    __syncthreads();
    const long long* p = (const long long*)ei;
    long long stride = E / blockDim.x;
    if (stride < 1) stride = 1;
    long long idx = (long long)threadIdx.x * stride;
    if (idx < E) {  // first E int64 slots are in-bounds under BOTH interpretations
        long long v = p[idx];
        if (v < 0 || v >= (long long)n) ok = 0;
    }
    __syncthreads();
    if (threadIdx.x == 0) {
        g_is64 = ok;
        g_b1zero = (b1[0] == 0.0f && b1[1] == 0.0f &&
                    b1[2] == 0.0f && b1[3] == 0.0f) ? 1 : 0;
    }
}

// ---------------- node kernels ----------------

__global__ void k_init_deg(int n) {
    int i = blockIdx.x * blockDim.x + threadIdx.x;
    if (i < n) g_deg[i] = 1.0f;              // self-loop
}

__global__ void k_dinv(const float* __restrict__ x, int n) {
    int i = blockIdx.x * blockDim.x + threadIdx.x;
    if (i < n) {
        float di = rsqrtf(g_deg[i]);         // deg >= 1 always (self-loop)
        g_dinv[i] = di;
        float v = di * x[i];
        g_v[i] = v;
        g_s[i] = v;                          // self-loop contribution, layer 1
    }
}

// After layer-1 scatter: pre = dinv*s.
// Fast path  : val = dinv*pre; spos/sneg init with self-loop term.
// Fallback   : h = relu(pre*W1+b1); h2d = dinv*(h@W2); out init = h2d.
__global__ void k_mid(const float* __restrict__ W1, const float* __restrict__ b1,
                      const float* __restrict__ W2,
                      float4* __restrict__ out, int n) {
    int i = blockIdx.x * blockDim.x + threadIdx.x;
    if (i >= n) return;
    float di  = g_dinv[i];
    float pre = di * g_s[i];
    float val = di * pre;
    g_val [i] = val;
    g_spos[i] = fmaxf(val, 0.0f);            // self-loop contribution, layer 2
    g_sneg[i] = fmaxf(-val, 0.0f);
    // fallback representation (cheap; only used if b1 != 0)
    float h[4];
#pragma unroll
    for (int c = 0; c < 4; c++)
        h[c] = fmaxf(fmaf(pre, __ldg(&W1[c]), __ldg(&b1[c])), 0.0f);
    float4 v;
    v.x = di * (h[0]*__ldg(&W2[0]) + h[1]*__ldg(&W2[4]) + h[2]*__ldg(&W2[8])  + h[3]*__ldg(&W2[12]));
    v.y = di * (h[0]*__ldg(&W2[1]) + h[1]*__ldg(&W2[5]) + h[2]*__ldg(&W2[9])  + h[3]*__ldg(&W2[13]));
    v.z = di * (h[0]*__ldg(&W2[2]) + h[1]*__ldg(&W2[6]) + h[2]*__ldg(&W2[10]) + h[3]*__ldg(&W2[14]));
    v.w = di * (h[0]*__ldg(&W2[3]) + h[1]*__ldg(&W2[7]) + h[2]*__ldg(&W2[11]) + h[3]*__ldg(&W2[15]));
    g_h2d[i] = v;
    if (!g_b1zero) out[i] = v;               // fallback accumulates into out
}

__global__ void k_final(const float* __restrict__ W1, const float* __restrict__ W2,
                        const float* __restrict__ b2,
                        float4* __restrict__ out, int n) {
    int i = blockIdx.x * blockDim.x + threadIdx.x;
    if (i >= n) return;
    float di = g_dinv[i];
    if (g_b1zero) {
        // u_pos = max(W1,0)@W2 ; u_neg = max(-W1,0)@W2  (all L1/const hits)
        float gp[4], gn[4];
#pragma unroll
        for (int k = 0; k < 4; k++) {
            float w = __ldg(&W1[k]);
            gp[k] = fmaxf(w, 0.0f);
            gn[k] = fmaxf(-w, 0.0f);
        }
        float sp = g_spos[i], sn = g_sneg[i];
        float o[4];
#pragma unroll
        for (int c = 0; c < 4; c++) {
            float up = gp[0]*__ldg(&W2[0*4+c]) + gp[1]*__ldg(&W2[1*4+c])
                     + gp[2]*__ldg(&W2[2*4+c]) + gp[3]*__ldg(&W2[3*4+c]);
            float un = gn[0]*__ldg(&W2[0*4+c]) + gn[1]*__ldg(&W2[1*4+c])
                     + gn[2]*__ldg(&W2[2*4+c]) + gn[3]*__ldg(&W2[3*4+c]);
            o[c] = fmaf(di, sp*up + sn*un, __ldg(&b2[c]));
        }
        out[i] = make_float4(o[0], o[1], o[2], o[3]);
    } else {
        float4 o = out[i];
        out[i] = make_float4(fmaf(di, o.x, __ldg(&b2[0])),
                             fmaf(di, o.y, __ldg(&b2[1])),
                             fmaf(di, o.z, __ldg(&b2[2])),
                             fmaf(di, o.w, __ldg(&b2[3])));
    }
}

// ---------------- edge kernels (read edge_index directly, dtype-branched) ----

__device__ __forceinline__ int load_idx(const void* ei, int e, int is64) {
    return is64 ? (int)((const long long*)ei)[e] : ((const int*)ei)[e];
}

__global__ void k_deg(const void* __restrict__ ei, int E, int n) {
    int is64 = g_is64;
    int e0 = blockIdx.x * blockDim.x * EPT + threadIdx.x;
    for (int k = 0; k < EPT; k++) {
        int e = e0 + k * blockDim.x;
        if (e < E) {
            int d = load_idx(ei, e + E, is64);
            if ((unsigned)d < (unsigned)n) atomicAdd(&g_deg[d], 1.0f);
        }
    }
}

__global__ void k_scatter1(const void* __restrict__ ei, int E, int n) {
    int is64 = g_is64;
    int e0 = blockIdx.x * blockDim.x * EPT + threadIdx.x;
    for (int k = 0; k < EPT; k++) {
        int e = e0 + k * blockDim.x;
        if (e < E) {
            int s = load_idx(ei, e, is64);
            int d = load_idx(ei, e + E, is64);
            if ((unsigned)s < (unsigned)n && (unsigned)d < (unsigned)n)
                atomicAdd(&g_s[d], __ldg(&g_v[s]));
        }
    }
}

__global__ void k_scatter2(const void* __restrict__ ei,
                           float4* __restrict__ out, int E, int n) {
    int is64 = g_is64;
    int fast = g_b1zero;
    int e0 = blockIdx.x * blockDim.x * EPT + threadIdx.x;
    for (int k = 0; k < EPT; k++) {
        int e = e0 + k * blockDim.x;
        if (e < E) {
            int s = load_idx(ei, e, is64);
            int d = load_idx(ei, e + E, is64);
            if ((unsigned)s < (unsigned)n && (unsigned)d < (unsigned)n) {
                if (fast) {
                    float v = __ldg(&g_val[s]);
                    if (v >= 0.0f) atomicAdd(&g_spos[d], v);
                    else           atomicAdd(&g_sneg[d], -v);
                } else {
                    float4 m = __ldg(&g_h2d[s]);
                    float* p = reinterpret_cast<float*>(&out[d]);
                    asm volatile("red.global.add.v4.f32 [%0], {%1,%2,%3,%4};"
                                 :: "l"(p), "f"(m.x), "f"(m.y), "f"(m.z), "f"(m.w)
                                 : "memory");
                }
            }
        }
    }
}

// ---------------- launch ----------------

extern "C" void kernel_launch(void* const* d_in, const int* in_sizes, int n_in,
                              void* d_out, int out_size) {
    const float* x  = (const float*)d_in[0];
    const void*  ei = d_in[1];                 // [2, E], int32 or int64
    const float* W1 = (const float*)d_in[2];
    const float* b1 = (const float*)d_in[3];
    const float* W2 = (const float*)d_in[4];
    const float* b2 = (const float*)d_in[5];
    float4* out = (float4*)d_out;

    int n = in_sizes[0];            // N nodes (C_in = 1)
    int E = in_sizes[1] / 2;        // element count is dtype-independent

    int nb_node = (n + TB - 1) / TB;
    int nb_edge = (E + TB * EPT - 1) / (TB * EPT);

    k_probe    <<<1, TB>>>(ei, E, n, b1);
    k_init_deg <<<nb_node, TB>>>(n);
    k_deg      <<<nb_edge, TB>>>(ei, E, n);
    k_dinv     <<<nb_node, TB>>>(x, n);
    k_scatter1 <<<nb_edge, TB>>>(ei, E, n);
    k_mid      <<<nb_node, TB>>>(W1, b1, W2, out, n);
    k_scatter2 <<<nb_edge, TB>>>(ei, out, E, n);
    k_final    <<<nb_node, TB>>>(W1, W2, b2, out, n);
}

// round 5
// speedup vs baseline: 1.1272x; 1.0146x over previous
#include <cuda_runtime.h>

#define NN 500000   // N_NODES upper bound
#define TB 256
#define EPT 4       // edges per thread in edge kernels

// Scratch (no cudaMalloc allowed).
__device__ int    g_is64;        // 1 if edge_index is int64, 0 if int32
__device__ int    g_b1zero;      // 1 if b1 == 0 (enables scalar layer-2 path)
__device__ float  g_deg [NN];    // degree (float; exact for counts < 2^24)
__device__ float  g_dinv[NN];    // deg^{-1/2}
__device__ float  g_v   [NN];    // dinv[i] * x[i]          (gather source, layer 1)
__device__ float  g_s   [NN];    // layer-1 accumulator (init = self-loop term)
__device__ float  g_val [NN];    // dinv[i]^2 * s[i] = dinv*pre  (gather, layer 2 fast path)
__device__ float  g_spos[NN];    // Σ max(val[s],0) at dst  (init = self-loop)
__device__ float  g_sneg[NN];    // Σ max(-val[s],0) at dst (init = self-loop)
__device__ float4 g_h2d [NN];    // dinv[i]*(relu(pre)@W2)  (gather, fallback path)

// ---------------- probe + degree init (fused; saves a launch and aligns
// ncu's -s 5 capture window onto k_scatter2) ----------------
__global__ void k_probe_init(const void* ei, int E, int n, const float* __restrict__ b1) {
    int i = blockIdx.x * blockDim.x + threadIdx.x;
    if (i < n) g_deg[i] = 1.0f;              // self-loop
    if (blockIdx.x == 0) {
        // dtype probe: interpreted as int64, genuine int64 indices are in [0,n).
        // int32 misread as int64 gives lo + hi*2^32, out of range unless hi==0.
        __shared__ int ok;
        if (threadIdx.x == 0) ok = 1;
        __syncthreads();
        const long long* p = (const long long*)ei;
        long long stride = E / blockDim.x;
        if (stride < 1) stride = 1;
        long long idx = (long long)threadIdx.x * stride;
        if (idx < E) {   // first E int64 slots in-bounds under BOTH interpretations
            long long v = p[idx];
            if (v < 0 || v >= (long long)n) ok = 0;
        }
        __syncthreads();
        if (threadIdx.x == 0) {
            g_is64 = ok;
            g_b1zero = (b1[0] == 0.0f && b1[1] == 0.0f &&
                        b1[2] == 0.0f && b1[3] == 0.0f) ? 1 : 0;
        }
    }
}

// ---------------- node kernels ----------------

__global__ void k_dinv(const float* __restrict__ x, int n) {
    int i = blockIdx.x * blockDim.x + threadIdx.x;
    if (i < n) {
        float di = rsqrtf(g_deg[i]);         // deg >= 1 always (self-loop)
        g_dinv[i] = di;
        float v = di * x[i];
        g_v[i] = v;
        g_s[i] = v;                          // self-loop contribution, layer 1
    }
}

// After layer-1 scatter: pre = dinv*s.
// Fast path  : val = dinv*pre; spos/sneg init with self-loop term.
// Fallback   : h = relu(pre*W1+b1); h2d = dinv*(h@W2); out init = h2d.
__global__ void k_mid(const float* __restrict__ W1, const float* __restrict__ b1,
                      const float* __restrict__ W2,
                      float4* __restrict__ out, int n) {
    int i = blockIdx.x * blockDim.x + threadIdx.x;
    if (i >= n) return;
    float di  = g_dinv[i];
    float pre = di * g_s[i];
    float val = di * pre;
    g_val [i] = val;
    g_spos[i] = fmaxf(val, 0.0f);            // self-loop contribution, layer 2
    g_sneg[i] = fmaxf(-val, 0.0f);
    if (!g_b1zero) {                         // fallback representation (b1 != 0)
        float h[4];
#pragma unroll
        for (int c = 0; c < 4; c++)
            h[c] = fmaxf(fmaf(pre, __ldg(&W1[c]), __ldg(&b1[c])), 0.0f);
        float4 v;
        v.x = di * (h[0]*__ldg(&W2[0]) + h[1]*__ldg(&W2[4]) + h[2]*__ldg(&W2[8])  + h[3]*__ldg(&W2[12]));
        v.y = di * (h[0]*__ldg(&W2[1]) + h[1]*__ldg(&W2[5]) + h[2]*__ldg(&W2[9])  + h[3]*__ldg(&W2[13]));
        v.z = di * (h[0]*__ldg(&W2[2]) + h[1]*__ldg(&W2[6]) + h[2]*__ldg(&W2[10]) + h[3]*__ldg(&W2[14]));
        v.w = di * (h[0]*__ldg(&W2[3]) + h[1]*__ldg(&W2[7]) + h[2]*__ldg(&W2[11]) + h[3]*__ldg(&W2[15]));
        g_h2d[i] = v;
        out[i]   = v;                        // fallback accumulates into out
    }
}

__global__ void k_final(const float* __restrict__ W1, const float* __restrict__ W2,
                        const float* __restrict__ b2,
                        float4* __restrict__ out, int n) {
    int i = blockIdx.x * blockDim.x + threadIdx.x;
    if (i >= n) return;
    float di = g_dinv[i];
    if (g_b1zero) {
        float gp[4], gn[4];
#pragma unroll
        for (int k = 0; k < 4; k++) {
            float w = __ldg(&W1[k]);
            gp[k] = fmaxf(w, 0.0f);
            gn[k] = fmaxf(-w, 0.0f);
        }
        float sp = g_spos[i], sn = g_sneg[i];
        float o[4];
#pragma unroll
        for (int c = 0; c < 4; c++) {
            float up = gp[0]*__ldg(&W2[0*4+c]) + gp[1]*__ldg(&W2[1*4+c])
                     + gp[2]*__ldg(&W2[2*4+c]) + gp[3]*__ldg(&W2[3*4+c]);
            float un = gn[0]*__ldg(&W2[0*4+c]) + gn[1]*__ldg(&W2[1*4+c])
                     + gn[2]*__ldg(&W2[2*4+c]) + gn[3]*__ldg(&W2[3*4+c]);
            o[c] = fmaf(di, sp*up + sn*un, __ldg(&b2[c]));
        }
        out[i] = make_float4(o[0], o[1], o[2], o[3]);
    } else {
        float4 o = out[i];
        out[i] = make_float4(fmaf(di, o.x, __ldg(&b2[0])),
                             fmaf(di, o.y, __ldg(&b2[1])),
                             fmaf(di, o.z, __ldg(&b2[2])),
                             fmaf(di, o.w, __ldg(&b2[3])));
    }
}

// ---------------- edge kernels ----------------
// Edge-index loads use __ldcs (evict-first streaming) so the 128-256MB edge
// stream does NOT evict the ~12MB of L2-resident node arrays that the random
// gathers and atomics depend on.

__device__ __forceinline__ int load_idx_cs(const void* ei, int e, int is64) {
    if (is64) return (int)__ldcs(((const long long*)ei) + e);
    return __ldcs(((const int*)ei) + e);
}

__global__ void k_deg(const void* __restrict__ ei, int E, int n) {
    int is64 = g_is64;
    int e0 = blockIdx.x * blockDim.x * EPT + threadIdx.x;
    for (int k = 0; k < EPT; k++) {
        int e = e0 + k * blockDim.x;
        if (e < E) {
            int d = load_idx_cs(ei, e + E, is64);
            if ((unsigned)d < (unsigned)n) atomicAdd(&g_deg[d], 1.0f);
        }
    }
}

__global__ void k_scatter1(const void* __restrict__ ei, int E, int n) {
    int is64 = g_is64;
    int e0 = blockIdx.x * blockDim.x * EPT + threadIdx.x;
    for (int k = 0; k < EPT; k++) {
        int e = e0 + k * blockDim.x;
        if (e < E) {
            int s = load_idx_cs(ei, e, is64);
            int d = load_idx_cs(ei, e + E, is64);
            if ((unsigned)s < (unsigned)n && (unsigned)d < (unsigned)n)
                atomicAdd(&g_s[d], __ldg(&g_v[s]));
        }
    }
}

__global__ void k_scatter2(const void* __restrict__ ei,
                           float4* __restrict__ out, int E, int n) {
    int is64 = g_is64;
    int fast = g_b1zero;
    int e0 = blockIdx.x * blockDim.x * EPT + threadIdx.x;
    for (int k = 0; k < EPT; k++) {
        int e = e0 + k * blockDim.x;
        if (e < E) {
            int s = load_idx_cs(ei, e, is64);
            int d = load_idx_cs(ei, e + E, is64);
            if ((unsigned)s < (unsigned)n && (unsigned)d < (unsigned)n) {
                if (fast) {
                    float v = __ldg(&g_val[s]);
                    if (v >= 0.0f) atomicAdd(&g_spos[d], v);
                    else           atomicAdd(&g_sneg[d], -v);
                } else {
                    float4 m = __ldg(&g_h2d[s]);
                    float* p = reinterpret_cast<float*>(&out[d]);
                    asm volatile("red.global.add.v4.f32 [%0], {%1,%2,%3,%4};"
                                 :: "l"(p), "f"(m.x), "f"(m.y), "f"(m.z), "f"(m.w)
                                 : "memory");
                }
            }
        }
    }
}

// ---------------- launch ----------------

extern "C" void kernel_launch(void* const* d_in, const int* in_sizes, int n_in,
                              void* d_out, int out_size) {
    const float* x  = (const float*)d_in[0];
    const void*  ei = d_in[1];                 // [2, E], int32 or int64
    const float* W1 = (const float*)d_in[2];
    const float* b1 = (const float*)d_in[3];
    const float* W2 = (const float*)d_in[4];
    const float* b2 = (const float*)d_in[5];
    float4* out = (float4*)d_out;

    int n = in_sizes[0];            // N nodes (C_in = 1)
    int E = in_sizes[1] / 2;        // element count is dtype-independent

    int nb_node = (n + TB - 1) / TB;
    int nb_edge = (E + TB * EPT - 1) / (TB * EPT);

    // Launch order chosen so ncu (-s 5 -c 1) captures k_scatter2 (6th launch).
    k_probe_init <<<nb_node, TB>>>(ei, E, n, b1);   // 1
    k_deg        <<<nb_edge, TB>>>(ei, E, n);       // 2
    k_dinv       <<<nb_node, TB>>>(x, n);           // 3
    k_scatter1   <<<nb_edge, TB>>>(ei, E, n);       // 4
    k_mid        <<<nb_node, TB>>>(W1, b1, W2, out, n); // 5
    k_scatter2   <<<nb_edge, TB>>>(ei, out, E, n);  // 6  <-- profiled
    k_final      <<<nb_node, TB>>>(W1, W2, b2, out, n); // 7
}